// round 5
// baseline (speedup 1.0000x reference)
#include <cuda_runtime.h>
#include <cstdint>

#define DIMD 2048
#define NC 12
#define NC2 144
#define ROWS 64
#define NCTA 512
#define THREADS 512
#define DC 128
#define NCH 16
#define STR 148
#define EPSV 1e-5f

// smem byte offsets
#define OFF_CT 0                      // sCt [64][148] tf32 (37888 B)
#define OFF_B0 37888                  // WiT buf0 [128][148] (75776 B)
#define OFF_B1 113664                 // WiT buf1
#define OFF_LN 189440                 // LN partials (2048 B)
#define SMEM_BYTES 191488
// phase A aliases (float/word index) inside buf1
#define F1 (OFF_B1 / 4)
#define FOFF_X F1                     // x tile  [64][68]   (4352 w)
#define FOFF_WT (F1 + 4352)           // Wt tile [32][68]   (2176 w)
#define FOFF_RED F1                   // partials [8][64][32] (16384 w, after MMA)
#define FOFF_PV (F1 + 16384)          // pos/vel [64][24]   (1536 w)

__device__ __align__(16) uint32_t g_WiT[DIMD * NC2];  // [n][perm(k)] tf32 bits

__device__ __forceinline__ uint32_t smem_u32(const void* p) {
    uint32_t a;
    asm("{ .reg .u64 t; cvta.to.shared.u64 t, %1; cvt.u32.u64 %0, t; }"
        : "=r"(a) : "l"(p));
    return a;
}
__device__ __forceinline__ uint32_t to_tf32(float x) {
    uint32_t t;
    asm("cvt.rna.tf32.f32 %0, %1;" : "=r"(t) : "f"(x));
    return t;
}
// pair-permute within each k8 block: (k0,k4),(k1,k5),(k2,k6),(k3,k7)
__device__ __forceinline__ int kperm(int k) {
    return (k & ~7) + 2 * (k & 3) + ((k >> 2) & 1);
}
__device__ __forceinline__ void mma_tf32(float& c0, float& c1, float& c2, float& c3,
                                         uint32_t a0, uint32_t a1, uint32_t a2,
                                         uint32_t a3, uint32_t b0, uint32_t b1) {
    asm volatile(
        "mma.sync.aligned.m16n8k8.row.col.f32.tf32.tf32.f32 "
        "{%0,%1,%2,%3},{%4,%5,%6,%7},{%8,%9},{%0,%1,%2,%3};"
        : "+f"(c0), "+f"(c1), "+f"(c2), "+f"(c3)
        : "r"(a0), "r"(a1), "r"(a2), "r"(a3), "r"(b0), "r"(b1));
}

// ---- pre-kernel: Wi[k][n] fp32 -> g_WiT[n][perm(k)] tf32 ----
__global__ void wit_kernel(const float* __restrict__ Wi) {
    int idx = blockIdx.x * 256 + threadIdx.x;  // over 144*2048
    int k = idx >> 11;
    int n = idx & 2047;
    g_WiT[n * NC2 + kperm(k)] = to_tf32(Wi[idx]);
}

__global__ __launch_bounds__(THREADS, 1)
void gil_kernel(const float* __restrict__ x, const float* __restrict__ Wp,
                const float* __restrict__ bp, const float* __restrict__ Wv,
                const float* __restrict__ bv, const float* __restrict__ Wi,
                const float* __restrict__ bi, const float* __restrict__ gamma,
                const float* __restrict__ beta, float* __restrict__ out) {
    extern __shared__ char smc[];
    float* smf = (float*)smc;
    uint32_t* smu = (uint32_t*)smc;
    const int tid = threadIdx.x;
    const int w = tid >> 5, lane = tid & 31;
    const int gq = lane >> 2, tg = lane & 3;
    const int rowbase = blockIdx.x * ROWS;
    const uint32_t smem_base = smem_u32(smc);

    // -------- prologue: prefetch WiT chunk 0 into buf0 (overlaps phase A) ---
    {
        const char* src = (const char*)g_WiT;
#pragma unroll
        for (int j = 0; j < 9; j++) {
            int e = (tid + THREADS * j) * 16;  // byte index within 73728
            int n = e / 576;
            int ko = e - n * 576;
            uint32_t dst = smem_base + OFF_B0 + n * 592 + ko;
            asm volatile("cp.async.ca.shared.global [%0], [%1], 16;"
                         :: "r"(dst), "l"(src + e) : "memory");
        }
        asm volatile("cp.async.commit_group;" ::: "memory");
    }

    // ====== Phase A (tensor): pos/vel = x @ [Wp|Wv], K split 8-way ==========
    // warp w: k8-slice k8w = w&7 (within each 64-k chunk), n-half nh = w>>3
    const int k8w = w & 7;
    const int nh = w >> 3;
    float pa[8][4];
#pragma unroll
    for (int i = 0; i < 8; i++)
#pragma unroll
        for (int q = 0; q < 4; q++) pa[i][q] = 0.f;

    for (int kc = 0; kc < DIMD / 64; kc++) {
        if (kc) __syncthreads();
        // stage x chunk [64 rows x 64 k] tf32, pair-permuted, stride 68
#pragma unroll
        for (int j = 0; j < 2; j++) {
            int i4 = tid * 2 + j;
            int r = i4 >> 4, kq = i4 & 15;
            float4 v = *(const float4*)(x + (rowbase + r) * DIMD + kc * 64 + kq * 4);
            int base = FOFF_X + r * 68 + (kq >> 1) * 8 + (kq & 1);
            smu[base + 0] = to_tf32(v.x);
            smu[base + 2] = to_tf32(v.y);
            smu[base + 4] = to_tf32(v.z);
            smu[base + 6] = to_tf32(v.w);
        }
        // stage W chunk [32 n x 64 k] tf32 (n>=24 zero), pair-permuted
#pragma unroll
        for (int j = 0; j < 4; j++) {
            int i = tid + THREADS * j;  // < 2048
            int n = i >> 6, k = i & 63;
            float wv = 0.f;
            if (n < NC) wv = Wp[(kc * 64 + k) * NC + n];
            else if (n < 2 * NC) wv = Wv[(kc * 64 + k) * NC + n - NC];
            smu[FOFF_WT + n * 68 + kperm(k)] = to_tf32(wv);
        }
        __syncthreads();

        const uint32_t* pA = smu + FOFF_X + gq * 68 + k8w * 8 + 2 * tg;
        const uint32_t* pB = smu + FOFF_WT + (nh * 16 + gq) * 68 + k8w * 8 + 2 * tg;
        uint2 b0 = *(const uint2*)(pB);
        uint2 b1 = *(const uint2*)(pB + 8 * 68);
#pragma unroll
        for (int m = 0; m < 4; m++) {
            uint2 a02 = *(const uint2*)(pA + m * 16 * 68);
            uint2 a13 = *(const uint2*)(pA + (m * 16 + 8) * 68);
            mma_tf32(pa[2 * m][0], pa[2 * m][1], pa[2 * m][2], pa[2 * m][3],
                     a02.x, a13.x, a02.y, a13.y, b0.x, b0.y);
            mma_tf32(pa[2 * m + 1][0], pa[2 * m + 1][1], pa[2 * m + 1][2],
                     pa[2 * m + 1][3], a02.x, a13.x, a02.y, a13.y, b1.x, b1.y);
        }
    }
    __syncthreads();  // done reading sX/sWt; reuse region for sRed
    // write per-slice partials
#pragma unroll
    for (int m = 0; m < 4; m++) {
#pragma unroll
        for (int j = 0; j < 2; j++) {
            int n = (2 * nh + j) * 8 + 2 * tg;
            float* dst = smf + FOFF_RED + k8w * 2048 + (m * 16 + gq) * 32 + n;
            *(float2*)dst = make_float2(pa[2 * m + j][0], pa[2 * m + j][1]);
            *(float2*)(dst + 8 * 32) = make_float2(pa[2 * m + j][2], pa[2 * m + j][3]);
        }
    }
    __syncthreads();
    // reduce 8 k-slices + bias -> sPV [64][24]
#pragma unroll
    for (int q = 0; q < 3; q++) {
        int o = tid + THREADS * q;  // < 1536
        int row = o / 24, c = o - row * 24;
        float v = 0.f;
#pragma unroll
        for (int s = 0; s < 8; s++) v += smf[FOFF_RED + s * 2048 + row * 32 + c];
        v += (c < NC) ? bp[c] : bv[c - NC];
        smf[FOFF_PV + row * 24 + c] = v;
    }
    __syncthreads();

    // ============ Phase B: sCt[row][perm(k)] = tf32(pos_i * vel_j) ==========
    for (int t = tid; t < ROWS * NC2; t += THREADS) {
        int row = t / NC2;
        int k = t - row * NC2;
        int i = k / NC, j = k - i * NC;
        float ct = smf[FOFF_PV + row * 24 + i] * smf[FOFF_PV + row * 24 + NC + j];
        smu[row * STR + kperm(k)] = to_tf32(ct);
    }
    __syncthreads();  // sCt/sPV settled before prefetch overwrites buf1

    // ================= Phase C: chunk loop, paired-LDS tf32 mma =============
    const int r16 = (w & 3) * 16;
    const int cg = w >> 2;
    const int rowA = rowbase + r16 + gq;
    const int rowB = rowA + 8;
    float lsA = 0.f, qA = 0.f, lsB = 0.f, qB = 0.f;

    for (int c = 0; c < NCH; c++) {
        if (c < NCH - 1) {
            int nn0 = (c + 1) * DC;
            const char* src = (const char*)g_WiT + nn0 * NC2 * 4;
            uint32_t bufoff = ((c + 1) & 1) ? OFF_B1 : OFF_B0;
#pragma unroll
            for (int j = 0; j < 9; j++) {
                int e = (tid + THREADS * j) * 16;
                int n = e / 576;
                int ko = e - n * 576;
                uint32_t dst = smem_base + bufoff + n * 592 + ko;
                asm volatile("cp.async.ca.shared.global [%0], [%1], 16;"
                             :: "r"(dst), "l"(src + e) : "memory");
            }
            asm volatile("cp.async.commit_group;" ::: "memory");
            asm volatile("cp.async.wait_group 1;" ::: "memory");
        } else {
            asm volatile("cp.async.wait_group 0;" ::: "memory");
        }
        __syncthreads();

        const uint32_t* B = smu + ((c & 1) ? OFF_B1 : OFF_B0) / 4;
        float acc[4][4];
#pragma unroll
        for (int nt = 0; nt < 4; nt++)
#pragma unroll
            for (int q = 0; q < 4; q++) acc[nt][q] = 0.f;

        const uint32_t* Ar0 = smu + (r16 + gq) * STR + 2 * tg;
        const uint32_t* Ar1 = Ar0 + 8 * STR;
        const uint32_t* Bb = B + (cg * 32 + gq) * STR + 2 * tg;
#pragma unroll
        for (int k8 = 0; k8 < 18; k8++) {
            uint2 a02 = *(const uint2*)(Ar0 + k8 * 8);  // (a0, a2)
            uint2 a13 = *(const uint2*)(Ar1 + k8 * 8);  // (a1, a3)
#pragma unroll
            for (int nt = 0; nt < 4; nt++) {
                uint2 b = *(const uint2*)(Bb + nt * 8 * STR + k8 * 8);  // (b0, b1)
                mma_tf32(acc[nt][0], acc[nt][1], acc[nt][2], acc[nt][3],
                         a02.x, a13.x, a02.y, a13.y, b.x, b.y);
            }
        }

        // epilogue: y = inter + x + bi ; store ; LN partials
        int cbase = c * DC + cg * 32;
#pragma unroll
        for (int nt = 0; nt < 4; nt++) {
            int col = cbase + nt * 8 + 2 * tg;
            float2 biv = *(const float2*)(bi + col);
            float2 xa = *(const float2*)(x + rowA * DIMD + col);
            float y0 = acc[nt][0] + xa.x + biv.x;
            float y1 = acc[nt][1] + xa.y + biv.y;
            *(float2*)(out + rowA * DIMD + col) = make_float2(y0, y1);
            lsA += y0 + y1;
            qA += y0 * y0 + y1 * y1;
            float2 xb = *(const float2*)(x + rowB * DIMD + col);
            float y2 = acc[nt][2] + xb.x + biv.x;
            float y3 = acc[nt][3] + xb.y + biv.y;
            *(float2*)(out + rowB * DIMD + col) = make_float2(y2, y3);
            lsB += y2 + y3;
            qB += y2 * y2 + y3 * y3;
        }
        __syncthreads();  // done reading buf[c&1] before next prefetch
    }

    // ================= LN stats =============================================
#pragma unroll
    for (int off = 1; off <= 2; off <<= 1) {
        lsA += __shfl_xor_sync(0xffffffffu, lsA, off);
        qA += __shfl_xor_sync(0xffffffffu, qA, off);
        lsB += __shfl_xor_sync(0xffffffffu, lsB, off);
        qB += __shfl_xor_sync(0xffffffffu, qB, off);
    }
    float* sLN = (float*)(smc + OFF_LN);
    if (tg == 0) {
        int rA = r16 + gq, rB = rA + 8;
        *(float2*)(sLN + (cg * 64 + rA) * 2) = make_float2(lsA, qA);
        *(float2*)(sLN + (cg * 64 + rB) * 2) = make_float2(lsB, qB);
    }
    __syncthreads();
    float sumA = 0.f, ssqA = 0.f, sumB = 0.f, ssqB = 0.f;
#pragma unroll
    for (int g2 = 0; g2 < 4; g2++) {
        float2 va = *(const float2*)(sLN + (g2 * 64 + r16 + gq) * 2);
        float2 vb = *(const float2*)(sLN + (g2 * 64 + r16 + gq + 8) * 2);
        sumA += va.x; ssqA += va.y;
        sumB += vb.x; ssqB += vb.y;
    }
    float muA = sumA * (1.0f / DIMD);
    float rsA = rsqrtf(ssqA * (1.0f / DIMD) - muA * muA + EPSV);
    float muB = sumB * (1.0f / DIMD);
    float rsB = rsqrtf(ssqB * (1.0f / DIMD) - muB * muB + EPSV);

    // ================= Phase D: normalize own writes ========================
    for (int c = 0; c < NCH; c++) {
#pragma unroll
        for (int nt = 0; nt < 4; nt++) {
            int col = c * DC + cg * 32 + nt * 8 + 2 * tg;
            float2 g2 = *(const float2*)(gamma + col);
            float2 b2 = *(const float2*)(beta + col);
            float2 ya = *(const float2*)(out + rowA * DIMD + col);
            ya.x = (ya.x - muA) * rsA * g2.x + b2.x;
            ya.y = (ya.y - muA) * rsA * g2.y + b2.y;
            *(float2*)(out + rowA * DIMD + col) = ya;
            float2 yb = *(const float2*)(out + rowB * DIMD + col);
            yb.x = (yb.x - muB) * rsB * g2.x + b2.x;
            yb.y = (yb.y - muB) * rsB * g2.y + b2.y;
            *(float2*)(out + rowB * DIMD + col) = yb;
        }
    }
}

extern "C" void kernel_launch(void* const* d_in, const int* in_sizes, int n_in,
                              void* d_out, int out_size) {
    const float* x     = (const float*)d_in[0];
    const float* Wp    = (const float*)d_in[1];
    const float* bp    = (const float*)d_in[2];
    const float* Wv    = (const float*)d_in[3];
    const float* bv    = (const float*)d_in[4];
    const float* Wi    = (const float*)d_in[5];
    const float* bi    = (const float*)d_in[6];
    const float* gamma = (const float*)d_in[7];
    const float* beta  = (const float*)d_in[8];
    float* out = (float*)d_out;

    wit_kernel<<<(DIMD * NC2) / 256, 256>>>(Wi);
    cudaFuncSetAttribute(gil_kernel, cudaFuncAttributeMaxDynamicSharedMemorySize,
                         SMEM_BYTES);
    gil_kernel<<<NCTA, THREADS, SMEM_BYTES>>>(x, Wp, bp, Wv, bv, Wi, bi, gamma,
                                              beta, out);
}

// round 6
// speedup vs baseline: 1.2821x; 1.2821x over previous
#include <cuda_runtime.h>
#include <cstdint>

#define DIMD 2048
#define NC 12
#define NC2 144
#define ROWS 64
#define NCTA 512
#define THREADS 512
#define DC 128
#define NCH 16
#define STRA 148   // Ct natural stride (words): banks 20*gq+tg all-distinct
#define STRB 168   // B permuted stride (words): 168 % 32 == 8 -> uint2 conflict-free
#define EPSV 1e-5f

// ---- smem byte layout ----
#define OFF_CT 0                       // Ct [64][148] fp32-as-tf32 (37888 B)
#define OFF_B0 37888                   // WiT buf0 [128][168] (86016 B)
#define OFF_B1 123904                  // WiT buf1
#define OFF_LN 209920                  // LN partials (2048 B)
#define SMEM_BYTES 211968
// phase A staging aliases inside buf1 (bytes)
#define OFF_AX0 123904                 // x fp32 [64][68] (17408 B)
#define OFF_AX1 141312
#define OFF_AWT0 158720                // Wt tf32 [32][76] (9728 B)
#define OFF_AWT1 168448
// phase A reduction aliases (word indices)
#define FOFF_RED (OFF_B1 / 4)          // partials [8][64][32] (16384 w)
#define FOFF_PV (FOFF_RED + 16384)     // pos/vel [64][24] (1536 w)

__device__ __align__(16) uint32_t g_WiT[DIMD * NC2];  // [n][perm(k)] tf32
__device__ __align__(16) uint32_t g_WT[32 * DIMD];    // [n][k] tf32 (pos|vel|pad)

__device__ __forceinline__ uint32_t smem_u32(const void* p) {
    uint32_t a;
    asm("{ .reg .u64 t; cvta.to.shared.u64 t, %1; cvt.u32.u64 %0, t; }"
        : "=r"(a) : "l"(p));
    return a;
}
__device__ __forceinline__ uint32_t to_tf32(float x) {
    uint32_t t;
    asm("cvt.rna.tf32.f32 %0, %1;" : "=r"(t) : "f"(x));
    return t;
}
// pair-permute within each k8 block: pos 2j <- k=j, pos 2j+1 <- k=j+4
__device__ __forceinline__ int kperm(int k) {
    return (k & ~7) + 2 * (k & 3) + ((k >> 2) & 1);
}
__device__ __forceinline__ void mma_tf32(float& c0, float& c1, float& c2, float& c3,
                                         uint32_t a0, uint32_t a1, uint32_t a2,
                                         uint32_t a3, uint32_t b0, uint32_t b1) {
    asm volatile(
        "mma.sync.aligned.m16n8k8.row.col.f32.tf32.tf32.f32 "
        "{%0,%1,%2,%3},{%4,%5,%6,%7},{%8,%9},{%0,%1,%2,%3};"
        : "+f"(c0), "+f"(c1), "+f"(c2), "+f"(c3)
        : "r"(a0), "r"(a1), "r"(a2), "r"(a3), "r"(b0), "r"(b1));
}
__device__ __forceinline__ void cpa16(uint32_t dst, const void* src) {
    asm volatile("cp.async.ca.shared.global [%0], [%1], 16;"
                 :: "r"(dst), "l"(src) : "memory");
}

// ---- pre-kernels ----
__global__ void wit_kernel(const float* __restrict__ Wi) {
    int idx = blockIdx.x * 256 + threadIdx.x;  // 144*2048
    int k = idx >> 11;
    int n = idx & 2047;
    g_WiT[n * NC2 + kperm(k)] = to_tf32(Wi[idx]);
}
__global__ void wt_kernel(const float* __restrict__ Wp, const float* __restrict__ Wv) {
    int idx = blockIdx.x * 256 + threadIdx.x;  // 32*2048
    int n = idx >> 11;
    int k = idx & 2047;
    float v = 0.f;
    if (n < NC) v = Wp[k * NC + n];
    else if (n < 2 * NC) v = Wv[k * NC + n - NC];
    g_WT[idx] = to_tf32(v);
}

__global__ __launch_bounds__(THREADS, 1)
void gil_kernel(const float* __restrict__ x, const float* __restrict__ Wp,
                const float* __restrict__ bp, const float* __restrict__ Wv,
                const float* __restrict__ bv, const float* __restrict__ Wi,
                const float* __restrict__ bi, const float* __restrict__ gamma,
                const float* __restrict__ beta, float* __restrict__ out) {
    extern __shared__ char smc[];
    float* smf = (float*)smc;
    uint32_t* smu = (uint32_t*)smc;
    const int tid = threadIdx.x;
    const int w = tid >> 5, lane = tid & 31;
    const int gq = lane >> 2, tg = lane & 3;
    const int rowbase = blockIdx.x * ROWS;
    const uint32_t smem_base = smem_u32(smc);

    // -------- prefetch WiT chunk 0 into buf0 (group; overlaps phase A) -----
    {
        const char* src = (const char*)g_WiT;
#pragma unroll
        for (int j = 0; j < 9; j++) {
            int e = (tid + THREADS * j) * 16;
            int n = e / 576;
            int ko = e - n * 576;
            cpa16(smem_base + OFF_B0 + n * 672 + ko, src + e);
        }
        asm volatile("cp.async.commit_group;" ::: "memory");
    }
    // -------- phase A stage kc=0 --------------------------------------------
    {
#pragma unroll
        for (int j = 0; j < 2; j++) {
            int gi = tid + THREADS * j;  // < 1024
            int r = gi >> 4, kq = gi & 15;
            cpa16(smem_base + OFF_AX0 + r * 272 + kq * 16,
                  x + (rowbase + r) * DIMD + kq * 4);
        }
        {
            int n = tid >> 4, kq = tid & 15;
            cpa16(smem_base + OFF_AWT0 + n * 304 + kq * 16,
                  g_WT + n * DIMD + kq * 4);
        }
        asm volatile("cp.async.commit_group;" ::: "memory");
    }

    // ====== Phase A (tensor): pos/vel = x @ [Wp|Wv], K split 8-way ==========
    const int k8w = w & 7;
    const int nh = w >> 3;
    float pa[8][4];
#pragma unroll
    for (int i = 0; i < 8; i++)
#pragma unroll
        for (int q = 0; q < 4; q++) pa[i][q] = 0.f;

    for (int kc = 0; kc < DIMD / 64; kc++) {
        if (kc < DIMD / 64 - 1) {  // stage kc+1 into alternate buffers
            int kn = kc + 1;
            uint32_t axd = ((kn & 1) ? OFF_AX1 : OFF_AX0);
            uint32_t awd = ((kn & 1) ? OFF_AWT1 : OFF_AWT0);
#pragma unroll
            for (int j = 0; j < 2; j++) {
                int gi = tid + THREADS * j;
                int r = gi >> 4, kq = gi & 15;
                cpa16(smem_base + axd + r * 272 + kq * 16,
                      x + (rowbase + r) * DIMD + kn * 64 + kq * 4);
            }
            {
                int n = tid >> 4, kq = tid & 15;
                cpa16(smem_base + awd + n * 304 + kq * 16,
                      g_WT + n * DIMD + kn * 64 + kq * 4);
            }
            asm volatile("cp.async.commit_group;" ::: "memory");
            asm volatile("cp.async.wait_group 1;" ::: "memory");
        } else {
            asm volatile("cp.async.wait_group 0;" ::: "memory");
        }
        __syncthreads();

        const float* X = (const float*)(smc + ((kc & 1) ? OFF_AX1 : OFF_AX0));
        const uint32_t* WT = (const uint32_t*)(smc + ((kc & 1) ? OFF_AWT1 : OFF_AWT0));
        int kb = k8w * 8 + tg;
        uint32_t wb0 = WT[(nh * 16 + gq) * 76 + kb];
        uint32_t wb0h = WT[(nh * 16 + gq) * 76 + kb + 4];
        uint32_t wb1 = WT[(nh * 16 + 8 + gq) * 76 + kb];
        uint32_t wb1h = WT[(nh * 16 + 8 + gq) * 76 + kb + 4];
#pragma unroll
        for (int m = 0; m < 4; m++) {
            const float* Xr = X + (m * 16 + gq) * 68 + k8w * 8 + tg;
            uint32_t a0 = to_tf32(Xr[0]);
            uint32_t a2 = to_tf32(Xr[4]);
            uint32_t a1 = to_tf32(Xr[8 * 68]);
            uint32_t a3 = to_tf32(Xr[8 * 68 + 4]);
            mma_tf32(pa[2 * m][0], pa[2 * m][1], pa[2 * m][2], pa[2 * m][3],
                     a0, a1, a2, a3, wb0, wb0h);
            mma_tf32(pa[2 * m + 1][0], pa[2 * m + 1][1], pa[2 * m + 1][2],
                     pa[2 * m + 1][3], a0, a1, a2, a3, wb1, wb1h);
        }
        __syncthreads();  // all warps done with this stage buffer
    }
    // write per-slice partials (RED aliases staging; all consumption done)
#pragma unroll
    for (int m = 0; m < 4; m++) {
#pragma unroll
        for (int j = 0; j < 2; j++) {
            int n = (2 * nh + j) * 8 + 2 * tg;
            float* dst = smf + FOFF_RED + k8w * 2048 + (m * 16 + gq) * 32 + n;
            *(float2*)dst = make_float2(pa[2 * m + j][0], pa[2 * m + j][1]);
            *(float2*)(dst + 8 * 32) = make_float2(pa[2 * m + j][2], pa[2 * m + j][3]);
        }
    }
    __syncthreads();
    // reduce 8 k-slices + bias -> sPV [64][24]
#pragma unroll
    for (int q = 0; q < 3; q++) {
        int o = tid + THREADS * q;  // < 1536
        int row = o / 24, c = o - row * 24;
        float v = 0.f;
#pragma unroll
        for (int s = 0; s < 8; s++) v += smf[FOFF_RED + s * 2048 + row * 32 + c];
        v += (c < NC) ? bp[c] : bv[c - NC];
        smf[FOFF_PV + row * 24 + c] = v;
    }
    __syncthreads();

    // ============ Phase B: sCt[row][k] natural layout =======================
    for (int t = tid; t < ROWS * NC2; t += THREADS) {
        int row = t / NC2;
        int k = t - row * NC2;
        int i = k / NC, j = k - i * NC;
        float ct = smf[FOFF_PV + row * 24 + i] * smf[FOFF_PV + row * 24 + NC + j];
        smu[row * STRA + k] = to_tf32(ct);
    }
    __syncthreads();

    // ================= Phase C: chunk loop ==================================
    const int r16 = (w & 3) * 16;
    const int cg = w >> 2;
    const int rowA = rowbase + r16 + gq;
    const int rowB = rowA + 8;
    float lsA = 0.f, qA = 0.f, lsB = 0.f, qB = 0.f;

    for (int c = 0; c < NCH; c++) {
        if (c < NCH - 1) {
            const char* src = (const char*)g_WiT + (c + 1) * DC * NC2 * 4;
            uint32_t bufoff = ((c + 1) & 1) ? OFF_B1 : OFF_B0;
#pragma unroll
            for (int j = 0; j < 9; j++) {
                int e = (tid + THREADS * j) * 16;
                int n = e / 576;
                int ko = e - n * 576;
                cpa16(smem_base + bufoff + n * 672 + ko, src + e);
            }
            asm volatile("cp.async.commit_group;" ::: "memory");
            asm volatile("cp.async.wait_group 1;" ::: "memory");
        } else {
            asm volatile("cp.async.wait_group 0;" ::: "memory");
        }
        __syncthreads();

        const uint32_t* Bb = smu + ((c & 1) ? OFF_B1 : OFF_B0) / 4 +
                             (cg * 32 + gq) * STRB + 2 * tg;
        const uint32_t* A0 = smu + (r16 + gq) * STRA + tg;
        const uint32_t* A1 = A0 + 8 * STRA;

        float acc[4][4];
#pragma unroll
        for (int nt = 0; nt < 4; nt++)
#pragma unroll
            for (int q = 0; q < 4; q++) acc[nt][q] = 0.f;

        uint32_t af[2][4];
        uint2 bf[2][4];
        // preload k8 = 0
        af[0][0] = A0[0]; af[0][1] = A1[0]; af[0][2] = A0[4]; af[0][3] = A1[4];
#pragma unroll
        for (int nt = 0; nt < 4; nt++) bf[0][nt] = *(const uint2*)(Bb + nt * 8 * STRB);

#pragma unroll
        for (int k8 = 0; k8 < 18; k8++) {
            int cur = k8 & 1, nxt = cur ^ 1;
            if (k8 < 17) {
                int ko = (k8 + 1) * 8;
                af[nxt][0] = A0[ko];
                af[nxt][1] = A1[ko];
                af[nxt][2] = A0[ko + 4];
                af[nxt][3] = A1[ko + 4];
#pragma unroll
                for (int nt = 0; nt < 4; nt++)
                    bf[nxt][nt] = *(const uint2*)(Bb + nt * 8 * STRB + ko);
            }
#pragma unroll
            for (int nt = 0; nt < 4; nt++)
                mma_tf32(acc[nt][0], acc[nt][1], acc[nt][2], acc[nt][3],
                         af[cur][0], af[cur][1], af[cur][2], af[cur][3],
                         bf[cur][nt].x, bf[cur][nt].y);
        }

        // epilogue: y = inter + x + bi ; store ; LN partials
        int cbase = c * DC + cg * 32;
#pragma unroll
        for (int nt = 0; nt < 4; nt++) {
            int col = cbase + nt * 8 + 2 * tg;
            float2 biv = *(const float2*)(bi + col);
            float2 xa = *(const float2*)(x + rowA * DIMD + col);
            float y0 = acc[nt][0] + xa.x + biv.x;
            float y1 = acc[nt][1] + xa.y + biv.y;
            *(float2*)(out + rowA * DIMD + col) = make_float2(y0, y1);
            lsA += y0 + y1;
            qA += y0 * y0 + y1 * y1;
            float2 xb = *(const float2*)(x + rowB * DIMD + col);
            float y2 = acc[nt][2] + xb.x + biv.x;
            float y3 = acc[nt][3] + xb.y + biv.y;
            *(float2*)(out + rowB * DIMD + col) = make_float2(y2, y3);
            lsB += y2 + y3;
            qB += y2 * y2 + y3 * y3;
        }
        __syncthreads();  // done reading buf[c&1] before next prefetch
    }

    // ================= LN stats =============================================
#pragma unroll
    for (int off = 1; off <= 2; off <<= 1) {
        lsA += __shfl_xor_sync(0xffffffffu, lsA, off);
        qA += __shfl_xor_sync(0xffffffffu, qA, off);
        lsB += __shfl_xor_sync(0xffffffffu, lsB, off);
        qB += __shfl_xor_sync(0xffffffffu, qB, off);
    }
    float* sLN = (float*)(smc + OFF_LN);
    if (tg == 0) {
        int rA = r16 + gq, rB = rA + 8;
        *(float2*)(sLN + (cg * 64 + rA) * 2) = make_float2(lsA, qA);
        *(float2*)(sLN + (cg * 64 + rB) * 2) = make_float2(lsB, qB);
    }
    __syncthreads();
    float sumA = 0.f, ssqA = 0.f, sumB = 0.f, ssqB = 0.f;
#pragma unroll
    for (int g2 = 0; g2 < 4; g2++) {
        float2 va = *(const float2*)(sLN + (g2 * 64 + r16 + gq) * 2);
        float2 vb = *(const float2*)(sLN + (g2 * 64 + r16 + gq + 8) * 2);
        sumA += va.x; ssqA += va.y;
        sumB += vb.x; ssqB += vb.y;
    }
    float muA = sumA * (1.0f / DIMD);
    float rsA = rsqrtf(ssqA * (1.0f / DIMD) - muA * muA + EPSV);
    float muB = sumB * (1.0f / DIMD);
    float rsB = rsqrtf(ssqB * (1.0f / DIMD) - muB * muB + EPSV);

    // ================= Phase D: normalize own writes ========================
    for (int c = 0; c < NCH; c++) {
#pragma unroll
        for (int nt = 0; nt < 4; nt++) {
            int col = c * DC + cg * 32 + nt * 8 + 2 * tg;
            float2 g2 = *(const float2*)(gamma + col);
            float2 b2 = *(const float2*)(beta + col);
            float2 ya = *(const float2*)(out + rowA * DIMD + col);
            ya.x = (ya.x - muA) * rsA * g2.x + b2.x;
            ya.y = (ya.y - muA) * rsA * g2.y + b2.y;
            *(float2*)(out + rowA * DIMD + col) = ya;
            float2 yb = *(const float2*)(out + rowB * DIMD + col);
            yb.x = (yb.x - muB) * rsB * g2.x + b2.x;
            yb.y = (yb.y - muB) * rsB * g2.y + b2.y;
            *(float2*)(out + rowB * DIMD + col) = yb;
        }
    }
}

extern "C" void kernel_launch(void* const* d_in, const int* in_sizes, int n_in,
                              void* d_out, int out_size) {
    const float* x     = (const float*)d_in[0];
    const float* Wp    = (const float*)d_in[1];
    const float* bp    = (const float*)d_in[2];
    const float* Wv    = (const float*)d_in[3];
    const float* bv    = (const float*)d_in[4];
    const float* Wi    = (const float*)d_in[5];
    const float* bi    = (const float*)d_in[6];
    const float* gamma = (const float*)d_in[7];
    const float* beta  = (const float*)d_in[8];
    float* out = (float*)d_out;

    wit_kernel<<<(DIMD * NC2) / 256, 256>>>(Wi);
    wt_kernel<<<(32 * DIMD) / 256, 256>>>(Wp, Wv);
    cudaFuncSetAttribute(gil_kernel, cudaFuncAttributeMaxDynamicSharedMemorySize,
                         SMEM_BYTES);
    gil_kernel<<<NCTA, THREADS, SMEM_BYTES>>>(x, Wp, bp, Wv, bv, Wi, bi, gamma,
                                              beta, out);
}

// round 8
// speedup vs baseline: 1.3225x; 1.0315x over previous
#include <cuda_runtime.h>
#include <cstdint>

#define DIMD 2048
#define NC 12
#define NC2 144
#define ROWS 64
#define NCTA 512
#define THREADS 512
#define DC 128
#define NCH 16
#define STRA 148   // Ct natural stride (words): banks 20*gq+tg all-distinct
#define STRB 168   // B permuted stride (words): 168 % 32 == 8 -> uint2 conflict-free
#define EPSV 1e-5f

// ---- smem byte layout ----
#define OFF_CT 0                       // Ct [64][148] tf32 (37888 B)
#define OFF_B0 37888                   // WiT buf0 [128][168] (86016 B)
#define OFF_B1 123904                  // WiT buf1
#define OFF_LN 209920                  // LN partials (2048 B)
#define SMEM_BYTES 211968
// phase A staging aliases inside buf1 (bytes)
#define OFF_AX0 123904                 // x fp32 [64][68] (17408 B)
#define OFF_AX1 141312
#define OFF_AWT0 158720                // Wt tf32 [32][76] (9728 B)
#define OFF_AWT1 168448
// phase A reduction aliases (word indices)
#define FOFF_RED (OFF_B1 / 4)          // partials [8][64][32] (16384 w)
#define FOFF_PV (FOFF_RED + 16384)     // pos/vel [64][24] (1536 w)

__device__ __align__(16) uint32_t g_WiT[DIMD * NC2];  // [n][perm(k)] tf32
__device__ __align__(16) uint32_t g_WT[32 * DIMD];    // [n][k] tf32 (pos|vel|pad)

__device__ __forceinline__ uint32_t smem_u32(const void* p) {
    uint32_t a;
    asm("{ .reg .u64 t; cvta.to.shared.u64 t, %1; cvt.u32.u64 %0, t; }"
        : "=r"(a) : "l"(p));
    return a;
}
__device__ __forceinline__ uint32_t to_tf32(float x) {
    uint32_t t;
    asm("cvt.rna.tf32.f32 %0, %1;" : "=r"(t) : "f"(x));
    return t;
}
// pair-permute within each k8 block: pos 2j <- k=j, pos 2j+1 <- k=j+4
__device__ __forceinline__ int kperm(int k) {
    return (k & ~7) + 2 * (k & 3) + ((k >> 2) & 1);
}
__device__ __forceinline__ void mma_tf32(float& c0, float& c1, float& c2, float& c3,
                                         uint32_t a0, uint32_t a1, uint32_t a2,
                                         uint32_t a3, uint32_t b0, uint32_t b1) {
    asm volatile(
        "mma.sync.aligned.m16n8k8.row.col.f32.tf32.tf32.f32 "
        "{%0,%1,%2,%3},{%4,%5,%6,%7},{%8,%9},{%0,%1,%2,%3};"
        : "+f"(c0), "+f"(c1), "+f"(c2), "+f"(c3)
        : "r"(a0), "r"(a1), "r"(a2), "r"(a3), "r"(b0), "r"(b1));
}
__device__ __forceinline__ void cpa16(uint32_t dst, const void* src) {
    asm volatile("cp.async.ca.shared.global [%0], [%1], 16;"
                 :: "r"(dst), "l"(src) : "memory");
}

// ---- pre-kernels ----
__global__ void wit_kernel(const float* __restrict__ Wi) {
    int idx = blockIdx.x * 256 + threadIdx.x;  // 144*2048
    int k = idx >> 11;
    int n = idx & 2047;
    g_WiT[n * NC2 + kperm(k)] = to_tf32(Wi[idx]);
}
__global__ void wt_kernel(const float* __restrict__ Wp, const float* __restrict__ Wv) {
    int idx = blockIdx.x * 256 + threadIdx.x;  // 32*2048
    int n = idx >> 11;
    int k = idx & 2047;
    float v = 0.f;
    if (n < NC) v = Wp[k * NC + n];
    else if (n < 2 * NC) v = Wv[k * NC + n - NC];
    g_WT[idx] = to_tf32(v);
}

__global__ __launch_bounds__(THREADS, 1)
void gil_kernel(const float* __restrict__ x, const float* __restrict__ Wp,
                const float* __restrict__ bp, const float* __restrict__ Wv,
                const float* __restrict__ bv, const float* __restrict__ Wi,
                const float* __restrict__ bi, const float* __restrict__ gamma,
                const float* __restrict__ beta, float* __restrict__ out) {
    extern __shared__ char smc[];
    float* smf = (float*)smc;
    uint32_t* smu = (uint32_t*)smc;
    const int tid = threadIdx.x;
    const int w = tid >> 5, lane = tid & 31;
    const int gq = lane >> 2, tg = lane & 3;
    const int rowbase = blockIdx.x * ROWS;
    const uint32_t smem_base = smem_u32(smc);

    // -------- prefetch WiT chunk 0 into buf0 (group; overlaps phase A) -----
    {
        const char* src = (const char*)g_WiT;
#pragma unroll
        for (int j = 0; j < 9; j++) {
            int e = (tid + THREADS * j) * 16;
            int n = e / 576;
            int ko = e - n * 576;
            cpa16(smem_base + OFF_B0 + n * 672 + ko, src + e);
        }
        asm volatile("cp.async.commit_group;" ::: "memory");
    }
    // -------- phase A stage kc=0 --------------------------------------------
    {
#pragma unroll
        for (int j = 0; j < 2; j++) {
            int gi = tid + THREADS * j;  // < 1024
            int r = gi >> 4, kq = gi & 15;
            cpa16(smem_base + OFF_AX0 + r * 272 + kq * 16,
                  x + (rowbase + r) * DIMD + kq * 4);
        }
        {
            int n = tid >> 4, kq = tid & 15;
            cpa16(smem_base + OFF_AWT0 + n * 304 + kq * 16,
                  g_WT + n * DIMD + kq * 4);
        }
        asm volatile("cp.async.commit_group;" ::: "memory");
    }

    // ====== Phase A (tensor): pos/vel = x @ [Wp|Wv], K split 8-way ==========
    const int k8w = w & 7;
    const int nh = w >> 3;
    float pa[8][4];
#pragma unroll
    for (int i = 0; i < 8; i++)
#pragma unroll
        for (int q = 0; q < 4; q++) pa[i][q] = 0.f;

    for (int kc = 0; kc < DIMD / 64; kc++) {
        if (kc < DIMD / 64 - 1) {  // stage kc+1 into alternate buffers
            int kn = kc + 1;
            uint32_t axd = ((kn & 1) ? OFF_AX1 : OFF_AX0);
            uint32_t awd = ((kn & 1) ? OFF_AWT1 : OFF_AWT0);
#pragma unroll
            for (int j = 0; j < 2; j++) {
                int gi = tid + THREADS * j;
                int r = gi >> 4, kq = gi & 15;
                cpa16(smem_base + axd + r * 272 + kq * 16,
                      x + (rowbase + r) * DIMD + kn * 64 + kq * 4);
            }
            {
                int n = tid >> 4, kq = tid & 15;
                cpa16(smem_base + awd + n * 304 + kq * 16,
                      g_WT + n * DIMD + kn * 64 + kq * 4);
            }
            asm volatile("cp.async.commit_group;" ::: "memory");
            asm volatile("cp.async.wait_group 1;" ::: "memory");
        } else {
            asm volatile("cp.async.wait_group 0;" ::: "memory");
        }
        __syncthreads();  // all threads' copies for stage kc visible

        const float* X = (const float*)(smc + ((kc & 1) ? OFF_AX1 : OFF_AX0));
        const uint32_t* WT = (const uint32_t*)(smc + ((kc & 1) ? OFF_AWT1 : OFF_AWT0));
        int kb = k8w * 8 + tg;
        uint32_t wb0 = WT[(nh * 16 + gq) * 76 + kb];
        uint32_t wb0h = WT[(nh * 16 + gq) * 76 + kb + 4];
        uint32_t wb1 = WT[(nh * 16 + 8 + gq) * 76 + kb];
        uint32_t wb1h = WT[(nh * 16 + 8 + gq) * 76 + kb + 4];
#pragma unroll
        for (int m = 0; m < 4; m++) {
            const float* Xr = X + (m * 16 + gq) * 68 + k8w * 8 + tg;
            uint32_t a0 = to_tf32(Xr[0]);
            uint32_t a2 = to_tf32(Xr[4]);
            uint32_t a1 = to_tf32(Xr[8 * 68]);
            uint32_t a3 = to_tf32(Xr[8 * 68 + 4]);
            mma_tf32(pa[2 * m][0], pa[2 * m][1], pa[2 * m][2], pa[2 * m][3],
                     a0, a1, a2, a3, wb0, wb0h);
            mma_tf32(pa[2 * m + 1][0], pa[2 * m + 1][1], pa[2 * m + 1][2],
                     pa[2 * m + 1][3], a0, a1, a2, a3, wb1, wb1h);
        }
        __syncthreads();  // all warps done with this stage buffer
    }
    // write per-slice partials (RED aliases staging; all consumption done)
#pragma unroll
    for (int m = 0; m < 4; m++) {
#pragma unroll
        for (int j = 0; j < 2; j++) {
            int n = (2 * nh + j) * 8 + 2 * tg;
            float* dst = smf + FOFF_RED + k8w * 2048 + (m * 16 + gq) * 32 + n;
            *(float2*)dst = make_float2(pa[2 * m + j][0], pa[2 * m + j][1]);
            *(float2*)(dst + 8 * 32) = make_float2(pa[2 * m + j][2], pa[2 * m + j][3]);
        }
    }
    __syncthreads();
    // reduce 8 k-slices + bias -> sPV [64][24]
#pragma unroll
    for (int q = 0; q < 3; q++) {
        int o = tid + THREADS * q;  // < 1536
        int row = o / 24, c = o - row * 24;
        float v = 0.f;
#pragma unroll
        for (int s = 0; s < 8; s++) v += smf[FOFF_RED + s * 2048 + row * 32 + c];
        v += (c < NC) ? bp[c] : bv[c - NC];
        smf[FOFF_PV + row * 24 + c] = v;
    }
    __syncthreads();

    // ============ Phase B: sCt[row][k] natural layout =======================
    for (int t = tid; t < ROWS * NC2; t += THREADS) {
        int row = t / NC2;
        int k = t - row * NC2;
        int i = k / NC, j = k - i * NC;
        float ct = smf[FOFF_PV + row * 24 + i] * smf[FOFF_PV + row * 24 + NC + j];
        smu[row * STRA + k] = to_tf32(ct);
    }
    __syncthreads();  // Ct visible to all warps

    // ===== Hoist A-fragments for this warp's 16 rows (reused all chunks) ====
    const int r16 = (w & 3) * 16;
    const int cg = w >> 2;
    const int rowA = rowbase + r16 + gq;
    const int rowB = rowA + 8;
    uint32_t af[18][4];
    {
        const uint32_t* A0 = smu + (r16 + gq) * STRA + tg;
        const uint32_t* A1 = A0 + 8 * STRA;
#pragma unroll
        for (int k8 = 0; k8 < 18; k8++) {
            af[k8][0] = A0[k8 * 8];
            af[k8][1] = A1[k8 * 8];
            af[k8][2] = A0[k8 * 8 + 4];
            af[k8][3] = A1[k8 * 8 + 4];
        }
    }

    // ================= Phase C: chunk loop ==================================
    float lsA = 0.f, qA = 0.f, lsB = 0.f, qB = 0.f;

    for (int c = 0; c < NCH; c++) {
        if (c < NCH - 1) {
            const char* src = (const char*)g_WiT + (c + 1) * DC * NC2 * 4;
            uint32_t bufoff = ((c + 1) & 1) ? OFF_B1 : OFF_B0;
#pragma unroll
            for (int j = 0; j < 9; j++) {
                int e = (tid + THREADS * j) * 16;
                int n = e / 576;
                int ko = e - n * 576;
                cpa16(smem_base + bufoff + n * 672 + ko, src + e);
            }
            asm volatile("cp.async.commit_group;" ::: "memory");
            asm volatile("cp.async.wait_group 1;" ::: "memory");
        } else {
            asm volatile("cp.async.wait_group 0;" ::: "memory");
        }
        __syncthreads();  // chunk c copies from ALL threads visible

        const uint32_t* Bb = smu + ((c & 1) ? OFF_B1 : OFF_B0) / 4 +
                             (cg * 32 + gq) * STRB + 2 * tg;
        float acc[4][4];
#pragma unroll
        for (int nt = 0; nt < 4; nt++)
#pragma unroll
            for (int q = 0; q < 4; q++) acc[nt][q] = 0.f;

#pragma unroll
        for (int k8 = 0; k8 < 18; k8++) {
            uint2 b0 = *(const uint2*)(Bb + 0 * 8 * STRB + k8 * 8);
            uint2 b1 = *(const uint2*)(Bb + 1 * 8 * STRB + k8 * 8);
            uint2 b2 = *(const uint2*)(Bb + 2 * 8 * STRB + k8 * 8);
            uint2 b3 = *(const uint2*)(Bb + 3 * 8 * STRB + k8 * 8);
            mma_tf32(acc[0][0], acc[0][1], acc[0][2], acc[0][3],
                     af[k8][0], af[k8][1], af[k8][2], af[k8][3], b0.x, b0.y);
            mma_tf32(acc[1][0], acc[1][1], acc[1][2], acc[1][3],
                     af[k8][0], af[k8][1], af[k8][2], af[k8][3], b1.x, b1.y);
            mma_tf32(acc[2][0], acc[2][1], acc[2][2], acc[2][3],
                     af[k8][0], af[k8][1], af[k8][2], af[k8][3], b2.x, b2.y);
            mma_tf32(acc[3][0], acc[3][1], acc[3][2], acc[3][3],
                     af[k8][0], af[k8][1], af[k8][2], af[k8][3], b3.x, b3.y);
        }

        // epilogue: y = inter + x + bi ; store ; LN partials
        int cbase = c * DC + cg * 32;
#pragma unroll
        for (int nt = 0; nt < 4; nt++) {
            int col = cbase + nt * 8 + 2 * tg;
            float2 biv = *(const float2*)(bi + col);
            float2 xa = *(const float2*)(x + rowA * DIMD + col);
            float y0 = acc[nt][0] + xa.x + biv.x;
            float y1 = acc[nt][1] + xa.y + biv.y;
            *(float2*)(out + rowA * DIMD + col) = make_float2(y0, y1);
            lsA += y0 + y1;
            qA += y0 * y0 + y1 * y1;
            float2 xb = *(const float2*)(x + rowB * DIMD + col);
            float y2 = acc[nt][2] + xb.x + biv.x;
            float y3 = acc[nt][3] + xb.y + biv.y;
            *(float2*)(out + rowB * DIMD + col) = make_float2(y2, y3);
            lsB += y2 + y3;
            qB += y2 * y2 + y3 * y3;
        }
        __syncthreads();  // done reading buf[c&1] before next prefetch
    }

    // ================= LN stats =============================================
#pragma unroll
    for (int off = 1; off <= 2; off <<= 1) {
        lsA += __shfl_xor_sync(0xffffffffu, lsA, off);
        qA += __shfl_xor_sync(0xffffffffu, qA, off);
        lsB += __shfl_xor_sync(0xffffffffu, lsB, off);
        qB += __shfl_xor_sync(0xffffffffu, qB, off);
    }
    float* sLN = (float*)(smc + OFF_LN);
    if (tg == 0) {
        int rA = r16 + gq, rB = rA + 8;
        *(float2*)(sLN + (cg * 64 + rA) * 2) = make_float2(lsA, qA);
        *(float2*)(sLN + (cg * 64 + rB) * 2) = make_float2(lsB, qB);
    }
    __syncthreads();
    float sumA = 0.f, ssqA = 0.f, sumB = 0.f, ssqB = 0.f;
#pragma unroll
    for (int g2 = 0; g2 < 4; g2++) {
        float2 va = *(const float2*)(sLN + (g2 * 64 + r16 + gq) * 2);
        float2 vb = *(const float2*)(sLN + (g2 * 64 + r16 + gq + 8) * 2);
        sumA += va.x; ssqA += va.y;
        sumB += vb.x; ssqB += vb.y;
    }
    float muA = sumA * (1.0f / DIMD);
    float rsA = rsqrtf(ssqA * (1.0f / DIMD) - muA * muA + EPSV);
    float muB = sumB * (1.0f / DIMD);
    float rsB = rsqrtf(ssqB * (1.0f / DIMD) - muB * muB + EPSV);

    // ================= Phase D: normalize own writes ========================
    for (int c = 0; c < NCH; c++) {
#pragma unroll
        for (int nt = 0; nt < 4; nt++) {
            int col = c * DC + cg * 32 + nt * 8 + 2 * tg;
            float2 g2 = *(const float2*)(gamma + col);
            float2 b2 = *(const float2*)(beta + col);
            float2 ya = *(const float2*)(out + rowA * DIMD + col);
            ya.x = (ya.x - muA) * rsA * g2.x + b2.x;
            ya.y = (ya.y - muA) * rsA * g2.y + b2.y;
            *(float2*)(out + rowA * DIMD + col) = ya;
            float2 yb = *(const float2*)(out + rowB * DIMD + col);
            yb.x = (yb.x - muB) * rsB * g2.x + b2.x;
            yb.y = (yb.y - muB) * rsB * g2.y + b2.y;
            *(float2*)(out + rowB * DIMD + col) = yb;
        }
    }
}

extern "C" void kernel_launch(void* const* d_in, const int* in_sizes, int n_in,
                              void* d_out, int out_size) {
    const float* x     = (const float*)d_in[0];
    const float* Wp    = (const float*)d_in[1];
    const float* bp    = (const float*)d_in[2];
    const float* Wv    = (const float*)d_in[3];
    const float* bv    = (const float*)d_in[4];
    const float* Wi    = (const float*)d_in[5];
    const float* bi    = (const float*)d_in[6];
    const float* gamma = (const float*)d_in[7];
    const float* beta  = (const float*)d_in[8];
    float* out = (float*)d_out;

    wit_kernel<<<(DIMD * NC2) / 256, 256>>>(Wi);
    wt_kernel<<<(32 * DIMD) / 256, 256>>>(Wp, Wv);
    cudaFuncSetAttribute(gil_kernel, cudaFuncAttributeMaxDynamicSharedMemorySize,
                         SMEM_BYTES);
    gil_kernel<<<NCTA, THREADS, SMEM_BYTES>>>(x, Wp, bp, Wv, bv, Wi, bi, gamma,
                                              beta, out);
}